// round 13
// baseline (speedup 1.0000x reference)
#include <cuda_runtime.h>
#include <math.h>

#define Bb 8
#define Hh 32
#define Ff 8
#define Xx 128
#define Tt 256
#define Tm1 255

typedef unsigned long long ull;

// ---------------- scratch (static device arrays; no allocations) ----------------
__device__ float  g_Gu[Bb*Xx*Hh*Ff];          // [b][x][i][f]
__device__ float  g_dHu[Bb*Hh*Xx*Tm1];        // [b][i][x][t]
__device__ float2 g_dXft[Xx*Bb*Tm1*Hh];       // [k][b][t][c]
__device__ float2 g_z0ft[Xx*Bb*Hh];           // [k][b][i]
__device__ float2 g_Zall[Xx*Bb*Tt*Hh];        // [k][b][t][i]
__device__ float2 g_Sfwd[Xx*Xx];              // [x][k]  shifted forward DFT
__device__ float2 g_Sinv[Xx*Xx];              // [k][x]  (real-part inverse, scaled)

// Chunked M buffer: M_t[i,j] for a 32-step time window, all x,b.
// Layout [x][b][tl][i*32+j], tl in [0,32). 268 MB, reused 8x per run.
__device__ float2 g_Mc[(size_t)Xx * Bb * 32 * 1024];

// ---------------- packed f32x2 helpers (sm_103a) ----------------
__device__ __forceinline__ ull pk2(float lo, float hi) {
    ull r;
    asm("mov.b64 %0, {%1, %2};" : "=l"(r) : "f"(lo), "f"(hi));
    return r;
}
__device__ __forceinline__ ull fma2(ull a, ull b, ull c) {
    ull d;
    asm("fma.rn.f32x2 %0, %1, %2, %3;" : "=l"(d) : "l"(a), "l"(b), "l"(c));
    return d;
}

// ---------------- K0: twiddle tables ----------------
__global__ void k0_tables() {
    int idx = blockIdx.x * blockDim.x + threadIdx.x;
    if (idx >= Xx * Xx) return;
    int k = idx >> 7, x = idx & 127;
    int m = ((k + 64) * x) & 127;
    float a = -6.2831853071795864769f * (float)m / 128.0f;
    g_Sfwd[x * Xx + k] = make_float2(cosf(a), sinf(a));
    int m2 = (k * x) & 127;
    float a2 = 6.2831853071795864769f * (float)m2 / 128.0f;
    float sc = ((x & 1) ? -1.0f : 1.0f) / 128.0f;
    g_Sinv[k * Xx + x] = make_float2(sc * cosf(a2), -sc * sinf(a2));
}

// ---------------- K1: Gu[b,x,i,f] = sum_h Gw[i,f,h] * z0[b,h,x] ----------------
__global__ void k1_gu(const float* __restrict__ z0, const float* __restrict__ Gw) {
    int b = blockIdx.x >> 7;
    int x = blockIdx.x & 127;
    __shared__ float zr[Hh];
    int t = threadIdx.x;  // 256
    if (t < Hh) zr[t] = z0[(b * Hh + t) * Xx + x];
    __syncthreads();
    int i = t >> 3, f = t & 7;
    const float* gw = Gw + (i * Ff + f) * Hh;
    float acc = 0.0f;
#pragma unroll
    for (int h = 0; h < Hh; h++) acc += gw[h] * zr[h];
    g_Gu[blockIdx.x * 256 + t] = acc;
}

// ---------------- K2: dHu[b,i,x,t] = sum_f Gu[b,x,i,f]*(xi[t+1]-xi[t]) ----------------
__global__ void k2_dhu(const float* __restrict__ xi) {
    int b = blockIdx.x >> 7, x = blockIdx.x & 127;
    __shared__ float xs[Ff][Tt];
    __shared__ float gsh[256];
    int t = threadIdx.x;  // 256
#pragma unroll
    for (int f = 0; f < Ff; f++) xs[f][t] = xi[((b * Ff + f) * Xx + x) * Tt + t];
    gsh[t] = g_Gu[blockIdx.x * 256 + t];
    __syncthreads();
    if (t < Tm1) {
        float d[Ff];
#pragma unroll
        for (int f = 0; f < Ff; f++) d[f] = xs[f][t + 1] - xs[f][t];
        for (int i = 0; i < Hh; i++) {
            float acc = 0.0f;
#pragma unroll
            for (int f = 0; f < Ff; f++) acc += gsh[i * 8 + f] * d[f];
            g_dHu[((b * Hh + i) * Xx + x) * Tm1 + t] = acc;
        }
    }
}

// ---------------- K3b: z0ft[k,b,i] = sum_x S[k,x]*z0[b,i,x]; seeds Zall[t=0] ----------------
__global__ void k3b_z0ft(const float* __restrict__ z0) {
    int b = blockIdx.x >> 5, i = blockIdx.x & 31;  // 256 blocks
    __shared__ float row[Xx];
    int k = threadIdx.x;  // 128
    row[k] = z0[(b * Hh + i) * Xx + k];
    __syncthreads();
    float ar = 0.0f, ai = 0.0f;
    for (int x = 0; x < Xx; x++) {
        float2 s = g_Sfwd[x * Xx + k];
        float h = row[x];
        ar += s.x * h;
        ai += s.y * h;
    }
    float2 z = make_float2(ar, ai);
    g_z0ft[(k * Bb + b) * Hh + i] = z;
    g_Zall[((size_t)(k * Bb + b) * Tt + 0) * Hh + i] = z;
}

// ---------------- K3: dXft[k,b,t,c] = sum_x S[k,x]*dHu[b,c,x,t] ----------------
__global__ void k3_dft() {
    int bid = blockIdx.x;       // 1024 = 256 (b,c) * 4 chunks
    int chunk = bid & 3;
    int bi = bid >> 2;
    int b = bi >> 5, i = bi & 31;
    int tc = chunk * 64;
    __shared__ __align__(16) float tile[Xx][64];
    const float* src = g_dHu + (size_t)bi * Xx * Tm1;
    int tid = threadIdx.x;  // 256
    for (int e = tid; e < Xx * 64; e += 256) {
        int x = e >> 6, ttl = e & 63;
        int t = tc + ttl;
        tile[x][ttl] = (t < Tm1) ? src[x * Tm1 + t] : 0.0f;
    }
    __syncthreads();
    int k = tid & 127, th = tid >> 7;
    float ar[32], ai[32];
#pragma unroll
    for (int q = 0; q < 32; q++) { ar[q] = 0.0f; ai[q] = 0.0f; }
    for (int x = 0; x < Xx; x++) {
        float2 s = g_Sfwd[x * Xx + k];
        const float4* hp = (const float4*)&tile[x][th * 32];
#pragma unroll
        for (int q4 = 0; q4 < 8; q4++) {
            float4 h = hp[q4];
            ar[q4 * 4 + 0] += s.x * h.x;  ai[q4 * 4 + 0] += s.y * h.x;
            ar[q4 * 4 + 1] += s.x * h.y;  ai[q4 * 4 + 1] += s.y * h.y;
            ar[q4 * 4 + 2] += s.x * h.z;  ai[q4 * 4 + 2] += s.y * h.z;
            ar[q4 * 4 + 3] += s.x * h.w;  ai[q4 * 4 + 3] += s.y * h.w;
        }
    }
#pragma unroll
    for (int q = 0; q < 32; q++) {
        int t = tc + th * 32 + q;
        if (t < Tm1) g_dXft[((k * Bb + b) * Tm1 + t) * Hh + i] = make_float2(ar[q], ai[q]);
    }
}

// ---------------- KG: M[u,i,j] = sum_c W[x,i,c,j] * dX[x,u,c] for one 32-step window ----
// Block = (x, i-quarter), 256 threads = 8 warps. Thread (it=tid&7, jt=(tid>>3)&3,
// st=tid>>5) computes an 8u x 1i x 8j complex tile with packed-f32x2 accumulators.
// W packed in SMEM as (Wr,Wr)/(-Wi,Wi) pairs, row-padded to 33 ull so each
// half-warp's W LDS.64 hits all 16 8B-banks (conflict-free). dx staged as
// (dr,di)/(di,dr); dx LDS are warp-uniform broadcasts.
__global__ void __launch_bounds__(256, 1)
kg_gemm(const float* __restrict__ Wr, const float* __restrict__ Wi, int t0) {
    extern __shared__ __align__(16) ull smg[];
    ull* Wrr = smg;              // [c][ii][j] rows: c-stride 264, ii-stride 33
    ull* Wni = Wrr + 8448;
    ull* dp  = Wni + 8448;       // [s<64][c<32] : (dr,di)
    ull* ds  = dp + 2048;        // [s][c]       : (di,dr)
    int x = blockIdx.x, iq = blockIdx.y;
    int tid = threadIdx.x;

    // pack W slice: i in [iq*8, iq*8+8)
    for (int e = tid; e < 8192; e += 256) {
        int ii = e >> 10;
        int c  = (e >> 5) & 31;
        int j  = e & 31;
        int i  = iq * 8 + ii;
        size_t g = (((size_t)x * Hh + i) * Hh + c) * Hh + j;
        float wr = Wr[g], wi = Wi[g];
        Wrr[c * 264 + ii * 33 + j] = pk2(wr, wr);
        Wni[c * 264 + ii * 33 + j] = pk2(-wi, wi);
    }

    int it = tid & 7;
    int jt = (tid >> 3) & 3;
    int st = tid >> 5;
    float2* Mx = g_Mc + (size_t)x * (Bb * 32 * 1024);

    for (int q = 0; q < 4; q++) {       // 4 iters x 64 u = 256 u (8 b x 32 tl)
        __syncthreads();                 // W ready / previous iter's reads done
        for (int e = tid; e < 2048; e += 256) {
            int s = e >> 5, c = e & 31;
            int b = 2 * q + (s >> 5);
            int t = t0 + (s & 31);
            float2 d = (t < Tm1)
                ? g_dXft[(((size_t)x * Bb + b) * Tm1 + t) * Hh + c]
                : make_float2(0.0f, 0.0f);
            dp[s * 32 + c] = pk2(d.x, d.y);
            ds[s * 32 + c] = pk2(d.y, d.x);
        }
        __syncthreads();

        ull acc[8][8];
#pragma unroll
        for (int uu = 0; uu < 8; uu++)
#pragma unroll
            for (int jj = 0; jj < 8; jj++) acc[uu][jj] = 0ULL;

#pragma unroll 1
        for (int c = 0; c < 32; c++) {
            ull dv[8], sv[8];
#pragma unroll
            for (int uu = 0; uu < 8; uu++) {
                dv[uu] = dp[(st * 8 + uu) * 32 + c];   // warp-uniform broadcast
                sv[uu] = ds[(st * 8 + uu) * 32 + c];
            }
            const ull* wrc = Wrr + c * 264 + it * 33 + jt * 8;
            const ull* wnc = Wni + c * 264 + it * 33 + jt * 8;
#pragma unroll
            for (int jj = 0; jj < 8; jj++) {
                ull wrv = wrc[jj];
                ull wnv = wnc[jj];
#pragma unroll
                for (int uu = 0; uu < 8; uu++) {
                    acc[uu][jj] = fma2(wnv, sv[uu], acc[uu][jj]);
                    acc[uu][jj] = fma2(wrv, dv[uu], acc[uu][jj]);
                }
            }
        }

        int i = iq * 8 + it;
#pragma unroll
        for (int uu = 0; uu < 8; uu++) {
            int s = st * 8 + uu;
            int b = 2 * q + (s >> 5), tl = s & 31;
            ull* dst = (ull*)(Mx + ((size_t)(b * 32 + tl) * 1024 + i * 32 + jt * 8));
#pragma unroll
            for (int p = 0; p < 4; p++) {
                ulonglong2 v;
                v.x = acc[uu][2 * p];
                v.y = acc[uu][2 * p + 1];
                ((ulonglong2*)dst)[p] = v;
            }
        }
    }
}

// ---------------- KS: scan z_{t+1} = (I + M_t) z_t over one window; warp = (x,b) ------
__device__ __forceinline__ void ks_step(const float4 (&cu)[16], float4 (&nx)[16],
                                        const float4* __restrict__ Mrow, int tl,
                                        int t0, int cnt,
                                        float2& z, float2* zw, int w, int l, int x) {
    if (tl + 1 < cnt) {   // prefetch next step's M row
        const float4* p = Mrow + (size_t)(tl + 1) * 512;
#pragma unroll
        for (int r = 0; r < 16; r++) nx[r] = p[r];
    }
    float ar = 0.0f, ai = 0.0f;
#pragma unroll
    for (int j = 0; j < 32; j++) {
        float2 zj = zw[j];
        float mr = (j & 1) ? cu[j >> 1].z : cu[j >> 1].x;
        float mi = (j & 1) ? cu[j >> 1].w : cu[j >> 1].y;
        ar += mr * zj.x - mi * zj.y;
        ai += mr * zj.y + mi * zj.x;
    }
    __syncwarp();
    z.x += ar; z.y += ai;
    zw[l] = z;
    g_Zall[((size_t)(x * Bb + w) * Tt + (t0 + tl + 1)) * Hh + l] = z;
    __syncwarp();
}

__global__ void __launch_bounds__(256, 1)
ks_scan(int t0, int cnt) {
    __shared__ float2 zsh[8][32];
    int x = blockIdx.x;
    int w = threadIdx.x >> 5, l = threadIdx.x & 31;

    float2 z = g_Zall[((size_t)(x * Bb + w) * Tt + t0) * Hh + l];
    zsh[w][l] = z;
    __syncwarp();

    const float4* Mrow =
        (const float4*)(g_Mc + (size_t)(x * Bb + w) * 32 * 1024 + l * 32);

    float4 mc[16], mn[16];
#pragma unroll
    for (int r = 0; r < 16; r++) mc[r] = Mrow[r];  // tl = 0

    for (int tl = 0; tl < cnt; tl += 2) {
        ks_step(mc, mn, Mrow, tl, t0, cnt, z, zsh[w], w, l, x);
        if (tl + 1 < cnt)
            ks_step(mn, mc, Mrow, tl + 1, t0, cnt, z, zsh[w], w, l, x);
    }
}

// ---------------- K5: real inverse DFT to output (b,i,x,t) ----------------
__global__ void k5_idft(float* __restrict__ out) {
    int bid = blockIdx.x;         // 2048 = 256 (b,i) * 8 chunks of 32 t
    int chunk = bid & 7, bi = bid >> 3;
    int b = bi >> 5, i = bi & 31;
    int tc = chunk * 32;
    __shared__ __align__(16) float2 Zsh[Xx][32];
    int tid = threadIdx.x;  // 256
    for (int e = tid; e < Xx * 32; e += 256) {
        int k = e >> 5, ttl = e & 31;
        Zsh[k][ttl] = g_Zall[((size_t)(k * Bb + b) * Tt + tc + ttl) * Hh + i];
    }
    __syncthreads();
    int xx = tid & 127, th = tid >> 7;
    float acc[16];
#pragma unroll
    for (int q = 0; q < 16; q++) acc[q] = 0.0f;
    for (int k = 0; k < Xx; k++) {
        float2 cf = g_Sinv[k * Xx + xx];
        const float4* zp = (const float4*)&Zsh[k][th * 16];
#pragma unroll
        for (int q2 = 0; q2 < 8; q2++) {
            float4 z2 = zp[q2];
            acc[q2 * 2 + 0] += cf.x * z2.x + cf.y * z2.y;
            acc[q2 * 2 + 1] += cf.x * z2.z + cf.y * z2.w;
        }
    }
    float* dst = out + ((size_t)bi * Xx + xx) * Tt + tc + th * 16;
#pragma unroll
    for (int q4 = 0; q4 < 4; q4++) {
        ((float4*)dst)[q4] = make_float4(acc[q4 * 4 + 0], acc[q4 * 4 + 1],
                                         acc[q4 * 4 + 2], acc[q4 * 4 + 3]);
    }
}

// ---------------- launch ----------------
extern "C" void kernel_launch(void* const* d_in, const int* in_sizes, int n_in,
                              void* d_out, int out_size) {
    const float* z0 = (const float*)d_in[0];
    const float* xi = (const float*)d_in[1];
    // d_in[2] = A : provably unused (constant-in-t term cancels in dX)
    const float* Gw = (const float*)d_in[3];
    const float* Wr = (const float*)d_in[4];
    const float* Wi = (const float*)d_in[5];

    k0_tables<<<64, 256>>>();
    k1_gu<<<Bb * Xx, 256>>>(z0, Gw);
    k2_dhu<<<Bb * Xx, 256>>>(xi);
    k3b_z0ft<<<Bb * Hh, 128>>>(z0);
    k3_dft<<<Bb * Hh * 4, 256>>>();

    // KG smem: W pack 2*8448 ull + dx stage 2*2048 ull = 167936 B
    const int kg_smem = (8448 * 2 + 2048 * 2) * 8;
    cudaFuncSetAttribute(kg_gemm, cudaFuncAttributeMaxDynamicSharedMemorySize, kg_smem);

    for (int p = 0; p < 8; p++) {
        int t0 = p * 32;
        int cnt = (p == 7) ? 31 : 32;   // 7*32 + 31 = 255 steps
        kg_gemm<<<dim3(Xx, 4), 256, kg_smem>>>(Wr, Wi, t0);
        ks_scan<<<Xx, 256>>>(t0, cnt);
    }

    k5_idft<<<Bb * Hh * 8, 256>>>((float*)d_out);
}

// round 15
// speedup vs baseline: 1.4385x; 1.4385x over previous
#include <cuda_runtime.h>
#include <cuda_bf16.h>
#include <math.h>

#define Bb 8
#define Hh 32
#define Ff 8
#define Xx 128
#define Tt 256
#define Tm1 255

typedef unsigned int u32;

// ---------------- scratch (static device arrays; no allocations) ----------------
__device__ float  g_Gu[Bb*Xx*Hh*Ff];          // [b][x][i][f]
__device__ float  g_dHu[Bb*Hh*Xx*Tm1];        // [b][i][x][t]
__device__ float2 g_dXft[Xx*Bb*Tm1*Hh];       // [x][b][t][c]
__device__ float2 g_z0ft[Xx*Bb*Hh];           // [x][b][i]
__device__ float2 g_Zall[Xx*Bb*Tt*Hh];        // [x][b][t][i]
__device__ float2 g_Sfwd[Xx*Xx];
__device__ float2 g_Sinv[Xx*Xx];

// bf16-split GEMM operands (packed once per run)
__device__ __nv_bfloat16 g_Ah[(size_t)Xx*Bb*256*64];   // [x][b][t<256][k<64]
__device__ __nv_bfloat16 g_Al[(size_t)Xx*Bb*256*64];
__device__ __nv_bfloat16 g_Bh[(size_t)Xx*2048*64];     // [x][n<2048][k<64]
__device__ __nv_bfloat16 g_Bl[(size_t)Xx*2048*64];

// Chunked M buffer: [x][b][tl<32][i*32+j] complex fp32 (268 MB, reused 8x)
__device__ float2 g_Mc[(size_t)Xx * Bb * 32 * 1024];

// ---------------- warp mma helper (baseline PTX, sm_80+ feature set) ----------------
__device__ __forceinline__ void mma16816(float& c0, float& c1, float& c2, float& c3,
                                         u32 a0, u32 a1, u32 a2, u32 a3,
                                         u32 b0, u32 b1) {
    asm volatile(
        "mma.sync.aligned.m16n8k16.row.col.f32.bf16.bf16.f32 "
        "{%0,%1,%2,%3}, {%4,%5,%6,%7}, {%8,%9}, {%0,%1,%2,%3};"
        : "+f"(c0), "+f"(c1), "+f"(c2), "+f"(c3)
        : "r"(a0), "r"(a1), "r"(a2), "r"(a3), "r"(b0), "r"(b1));
}

// ---------------- K0: twiddle tables ----------------
__global__ void k0_tables() {
    int idx = blockIdx.x * blockDim.x + threadIdx.x;
    if (idx >= Xx * Xx) return;
    int k = idx >> 7, x = idx & 127;
    int m = ((k + 64) * x) & 127;
    float a = -6.2831853071795864769f * (float)m / 128.0f;
    g_Sfwd[x * Xx + k] = make_float2(cosf(a), sinf(a));
    int m2 = (k * x) & 127;
    float a2 = 6.2831853071795864769f * (float)m2 / 128.0f;
    float sc = ((x & 1) ? -1.0f : 1.0f) / 128.0f;
    g_Sinv[k * Xx + x] = make_float2(sc * cosf(a2), -sc * sinf(a2));
}

// ---------------- K1 ----------------
__global__ void k1_gu(const float* __restrict__ z0, const float* __restrict__ Gw) {
    int b = blockIdx.x >> 7;
    int x = blockIdx.x & 127;
    __shared__ float zr[Hh];
    int t = threadIdx.x;
    if (t < Hh) zr[t] = z0[(b * Hh + t) * Xx + x];
    __syncthreads();
    int i = t >> 3, f = t & 7;
    const float* gw = Gw + (i * Ff + f) * Hh;
    float acc = 0.0f;
#pragma unroll
    for (int h = 0; h < Hh; h++) acc += gw[h] * zr[h];
    g_Gu[blockIdx.x * 256 + t] = acc;
}

// ---------------- K2 ----------------
__global__ void k2_dhu(const float* __restrict__ xi) {
    int b = blockIdx.x >> 7, x = blockIdx.x & 127;
    __shared__ float xs[Ff][Tt];
    __shared__ float gsh[256];
    int t = threadIdx.x;
#pragma unroll
    for (int f = 0; f < Ff; f++) xs[f][t] = xi[((b * Ff + f) * Xx + x) * Tt + t];
    gsh[t] = g_Gu[blockIdx.x * 256 + t];
    __syncthreads();
    if (t < Tm1) {
        float d[Ff];
#pragma unroll
        for (int f = 0; f < Ff; f++) d[f] = xs[f][t + 1] - xs[f][t];
        for (int i = 0; i < Hh; i++) {
            float acc = 0.0f;
#pragma unroll
            for (int f = 0; f < Ff; f++) acc += gsh[i * 8 + f] * d[f];
            g_dHu[((b * Hh + i) * Xx + x) * Tm1 + t] = acc;
        }
    }
}

// ---------------- K3b ----------------
__global__ void k3b_z0ft(const float* __restrict__ z0) {
    int b = blockIdx.x >> 5, i = blockIdx.x & 31;
    __shared__ float row[Xx];
    int k = threadIdx.x;
    row[k] = z0[(b * Hh + i) * Xx + k];
    __syncthreads();
    float ar = 0.0f, ai = 0.0f;
    for (int x = 0; x < Xx; x++) {
        float2 s = g_Sfwd[x * Xx + k];
        float h = row[x];
        ar += s.x * h;
        ai += s.y * h;
    }
    float2 z = make_float2(ar, ai);
    g_z0ft[(k * Bb + b) * Hh + i] = z;
    g_Zall[((size_t)(k * Bb + b) * Tt + 0) * Hh + i] = z;
}

// ---------------- K3 ----------------
__global__ void k3_dft() {
    int bid = blockIdx.x;
    int chunk = bid & 3;
    int bi = bid >> 2;
    int b = bi >> 5, i = bi & 31;
    int tc = chunk * 64;
    __shared__ __align__(16) float tile[Xx][64];
    const float* src = g_dHu + (size_t)bi * Xx * Tm1;
    int tid = threadIdx.x;
    for (int e = tid; e < Xx * 64; e += 256) {
        int x = e >> 6, ttl = e & 63;
        int t = tc + ttl;
        tile[x][ttl] = (t < Tm1) ? src[x * Tm1 + t] : 0.0f;
    }
    __syncthreads();
    int k = tid & 127, th = tid >> 7;
    float ar[32], ai[32];
#pragma unroll
    for (int q = 0; q < 32; q++) { ar[q] = 0.0f; ai[q] = 0.0f; }
    for (int x = 0; x < Xx; x++) {
        float2 s = g_Sfwd[x * Xx + k];
        const float4* hp = (const float4*)&tile[x][th * 32];
#pragma unroll
        for (int q4 = 0; q4 < 8; q4++) {
            float4 h = hp[q4];
            ar[q4 * 4 + 0] += s.x * h.x;  ai[q4 * 4 + 0] += s.y * h.x;
            ar[q4 * 4 + 1] += s.x * h.y;  ai[q4 * 4 + 1] += s.y * h.y;
            ar[q4 * 4 + 2] += s.x * h.z;  ai[q4 * 4 + 2] += s.y * h.z;
            ar[q4 * 4 + 3] += s.x * h.w;  ai[q4 * 4 + 3] += s.y * h.w;
        }
    }
#pragma unroll
    for (int q = 0; q < 32; q++) {
        int t = tc + th * 32 + q;
        if (t < Tm1) g_dXft[((k * Bb + b) * Tm1 + t) * Hh + i] = make_float2(ar[q], ai[q]);
    }
}

// ---------------- KPA: pack A = dX into bf16 hi/lo [x][b][t<256][k<64] ----------------
// A[u,k]: k<32 -> re(dx[c=k]); k>=32 -> im(dx[c=k-32]). t=255 row zeroed.
__global__ void kp_a() {
    int xb = blockIdx.x;            // x*8+b
    int t = threadIdx.x;            // 256
    size_t dst = ((size_t)xb * 256 + t) * 64;
    if (t < Tm1) {
        const float2* dx = g_dXft + ((size_t)xb * Tm1 + t) * Hh;
#pragma unroll 8
        for (int c = 0; c < 32; c++) {
            float2 d = dx[c];
            __nv_bfloat16 h0 = __float2bfloat16(d.x);
            __nv_bfloat16 h1 = __float2bfloat16(d.y);
            g_Ah[dst + c]      = h0;
            g_Ah[dst + 32 + c] = h1;
            g_Al[dst + c]      = __float2bfloat16(d.x - __bfloat162float(h0));
            g_Al[dst + 32 + c] = __float2bfloat16(d.y - __bfloat162float(h1));
        }
    } else {
        for (int k = 0; k < 64; k++) {
            g_Ah[dst + k] = __float2bfloat16(0.0f);
            g_Al[dst + k] = __float2bfloat16(0.0f);
        }
    }
}

// ---------------- KPB: pack B from Wr/Wi into bf16 hi/lo [x][n<2048][k<64] ----------------
// n = i*64 + j*2 + p. p=0 (Mr): k<32 -> Wr[i,c,j], k>=32 -> -Wi[i,c,j]
//                    p=1 (Mi): k<32 -> Wi[i,c,j], k>=32 ->  Wr[i,c,j]
__global__ void kp_b(const float* __restrict__ Wr, const float* __restrict__ Wi) {
    int x = blockIdx.x;
    for (int e = threadIdx.x; e < 2048 * 64; e += 256) {
        int n = e >> 6, k = e & 63;
        int i = n >> 6, j = (n >> 1) & 31, p = n & 1;
        int c = k & 31;
        size_t wbase = (((size_t)x * Hh + i) * Hh + c) * Hh + j;
        float v;
        if (p == 0) v = (k < 32) ? Wr[wbase] : -Wi[wbase];
        else        v = (k < 32) ? Wi[wbase] :  Wr[wbase];
        __nv_bfloat16 hv = __float2bfloat16(v);
        size_t dst = ((size_t)x * 2048 + n) * 64 + k;
        g_Bh[dst] = hv;
        g_Bl[dst] = __float2bfloat16(v - __bfloat162float(hv));
    }
}

// ---------------- KG_MMA: legacy-HMMA M build for one 32-step window ----------------
// One block (512 thr, 16 warps) per x. Warp w owns u-tile [w*16, w*16+16)
// (u = b*32 + tl). A fragments (hi+lo) live in regs for the whole block.
// B (2048 n x 64 k, hi+lo) staged through SMEM in 16 chunks of 128 n-rows.
// SMEM rows use 36-b32 (144B) stride -> all fragment LDS are conflict-free
// (bank = 4*(lane>>2) + (lane&3), a permutation of 0..31).
// D = Ah*Bh + Ah*Bl + Al*Bh in fp32; c0/c1 = (re,im) of one (i,j) -> direct
// float2 store into g_Mc.
#define AROWS 36                     // b32 stride of staged rows
#define A_SM_WORDS (256 * AROWS)     // one A split
#define B_SM_WORDS (128 * AROWS)     // one B split
#define KG_SMEM_BYTES (2 * A_SM_WORDS * 4)   // 73728; B (2 splits) reuses this
__global__ void __launch_bounds__(512, 1)
kg_mma(int t0) {
    extern __shared__ __align__(16) u32 sm[];
    int x = blockIdx.x;
    int tid = threadIdx.x;
    int w = tid >> 5, lane = tid & 31;
    int g = lane >> 2, q = lane & 3;

    // ---- stage A (256 rows x 64 bf16, hi+lo), coalesced uint4 ----
    {
        const uint4* srcH = (const uint4*)(g_Ah + (size_t)x * Bb * 256 * 64);
        const uint4* srcL = (const uint4*)(g_Al + (size_t)x * Bb * 256 * 64);
        for (int e = tid; e < 256 * 8; e += 512) {
            int row = e >> 3, m = e & 7;     // row = b*32 + tl
            int b = row >> 5, tl = row & 31;
            int t = t0 + tl;                  // t<256 always (t0<=224)
            size_t s = ((size_t)b * 256 + t) * 8 + m;
            *(uint4*)(sm + row * AROWS + m * 4) = srcH[s];
            *(uint4*)(sm + A_SM_WORDS + row * AROWS + m * 4) = srcL[s];
        }
    }
    __syncthreads();

    // ---- extract A fragments into registers ----
    u32 ah[16], al[16];
    {
        int ub = w * 16 + g;
#pragma unroll
        for (int kc = 0; kc < 4; kc++) {
            int base = ub * AROWS + kc * 8 + q;
            ah[kc * 4 + 0] = sm[base];
            ah[kc * 4 + 1] = sm[base + 8 * AROWS];
            ah[kc * 4 + 2] = sm[base + 4];
            ah[kc * 4 + 3] = sm[base + 8 * AROWS + 4];
            al[kc * 4 + 0] = sm[A_SM_WORDS + base];
            al[kc * 4 + 1] = sm[A_SM_WORDS + base + 8 * AROWS];
            al[kc * 4 + 2] = sm[A_SM_WORDS + base + 4];
            al[kc * 4 + 3] = sm[A_SM_WORDS + base + 8 * AROWS + 4];
        }
    }
    __syncthreads();   // A region now reusable for B chunks

    // output base for this warp's u-tile
    int u0 = w * 16 + g;
    int b0 = u0 >> 5, tl0 = u0 & 31;
    float2* out0 = g_Mc + (((size_t)(x * Bb + b0)) * 32 + tl0) * 1024;

    const uint4* bsrcH = (const uint4*)(g_Bh + (size_t)x * 2048 * 64);
    const uint4* bsrcL = (const uint4*)(g_Bl + (size_t)x * 2048 * 64);

    for (int cc = 0; cc < 16; cc++) {
        // ---- stage B chunk: n in [cc*128, cc*128+128), hi+lo ----
        for (int e = tid; e < 128 * 8; e += 512) {
            int row = e >> 3, m = e & 7;
            size_t s = ((size_t)(cc * 128 + row)) * 8 + m;
            *(uint4*)(sm + row * AROWS + m * 4) = bsrcH[s];
            *(uint4*)(sm + B_SM_WORDS + row * AROWS + m * 4) = bsrcL[s];
        }
        __syncthreads();

        // ---- compute: 16 n8-tiles per chunk ----
#pragma unroll 2
        for (int tile = 0; tile < 16; tile++) {
            int nb = tile * 8;
            float c0 = 0.0f, c1 = 0.0f, c2 = 0.0f, c3 = 0.0f;
            u32 bh[8];
            int bbase = (nb + g) * AROWS + q;
#pragma unroll
            for (int kc = 0; kc < 4; kc++) {
                bh[kc * 2 + 0] = sm[bbase + kc * 8];
                bh[kc * 2 + 1] = sm[bbase + kc * 8 + 4];
                mma16816(c0, c1, c2, c3,
                         ah[kc * 4], ah[kc * 4 + 1], ah[kc * 4 + 2], ah[kc * 4 + 3],
                         bh[kc * 2], bh[kc * 2 + 1]);
            }
#pragma unroll
            for (int kc = 0; kc < 4; kc++) {
                u32 bl0 = sm[B_SM_WORDS + bbase + kc * 8];
                u32 bl1 = sm[B_SM_WORDS + bbase + kc * 8 + 4];
                mma16816(c0, c1, c2, c3,
                         ah[kc * 4], ah[kc * 4 + 1], ah[kc * 4 + 2], ah[kc * 4 + 3],
                         bl0, bl1);
            }
#pragma unroll
            for (int kc = 0; kc < 4; kc++) {
                mma16816(c0, c1, c2, c3,
                         al[kc * 4], al[kc * 4 + 1], al[kc * 4 + 2], al[kc * 4 + 3],
                         bh[kc * 2], bh[kc * 2 + 1]);
            }
            // store: (u0, ij) and (u0+8, ij); same b, tl+8
            int ij = (cc * 128 + nb) / 2 + q;
            out0[ij] = make_float2(c0, c1);
            out0[8 * 1024 + ij] = make_float2(c2, c3);
        }
        __syncthreads();
    }
}

// ---------------- KS: scan z_{t+1} = (I + M_t) z_t over one window; warp = (x,b) ------
__device__ __forceinline__ void ks_step(const float4 (&cu)[16], float4 (&nx)[16],
                                        const float4* __restrict__ Mrow, int tl,
                                        int t0, int cnt,
                                        float2& z, float2* zw, int w, int l, int x) {
    if (tl + 1 < cnt) {
        const float4* p = Mrow + (size_t)(tl + 1) * 512;
#pragma unroll
        for (int r = 0; r < 16; r++) nx[r] = p[r];
    }
    float ar = 0.0f, ai = 0.0f;
#pragma unroll
    for (int j = 0; j < 32; j++) {
        float2 zj = zw[j];
        float mr = (j & 1) ? cu[j >> 1].z : cu[j >> 1].x;
        float mi = (j & 1) ? cu[j >> 1].w : cu[j >> 1].y;
        ar += mr * zj.x - mi * zj.y;
        ai += mr * zj.y + mi * zj.x;
    }
    __syncwarp();
    z.x += ar; z.y += ai;
    zw[l] = z;
    g_Zall[((size_t)(x * Bb + w) * Tt + (t0 + tl + 1)) * Hh + l] = z;
    __syncwarp();
}

__global__ void __launch_bounds__(256, 1)
ks_scan(int t0, int cnt) {
    __shared__ float2 zsh[8][32];
    int x = blockIdx.x;
    int w = threadIdx.x >> 5, l = threadIdx.x & 31;

    float2 z = g_Zall[((size_t)(x * Bb + w) * Tt + t0) * Hh + l];
    zsh[w][l] = z;
    __syncwarp();

    const float4* Mrow =
        (const float4*)(g_Mc + (size_t)(x * Bb + w) * 32 * 1024 + l * 32);

    float4 mc[16], mn[16];
#pragma unroll
    for (int r = 0; r < 16; r++) mc[r] = Mrow[r];

    for (int tl = 0; tl < cnt; tl += 2) {
        ks_step(mc, mn, Mrow, tl, t0, cnt, z, zsh[w], w, l, x);
        if (tl + 1 < cnt)
            ks_step(mn, mc, Mrow, tl + 1, t0, cnt, z, zsh[w], w, l, x);
    }
}

// ---------------- K5: real inverse DFT to output (b,i,x,t) ----------------
__global__ void k5_idft(float* __restrict__ out) {
    int bid = blockIdx.x;
    int chunk = bid & 7, bi = bid >> 3;
    int b = bi >> 5, i = bi & 31;
    int tc = chunk * 32;
    __shared__ __align__(16) float2 Zsh[Xx][32];
    int tid = threadIdx.x;
    for (int e = tid; e < Xx * 32; e += 256) {
        int k = e >> 5, ttl = e & 31;
        Zsh[k][ttl] = g_Zall[((size_t)(k * Bb + b) * Tt + tc + ttl) * Hh + i];
    }
    __syncthreads();
    int xx = tid & 127, th = tid >> 7;
    float acc[16];
#pragma unroll
    for (int q = 0; q < 16; q++) acc[q] = 0.0f;
    for (int k = 0; k < Xx; k++) {
        float2 cf = g_Sinv[k * Xx + xx];
        const float4* zp = (const float4*)&Zsh[k][th * 16];
#pragma unroll
        for (int q2 = 0; q2 < 8; q2++) {
            float4 z2 = zp[q2];
            acc[q2 * 2 + 0] += cf.x * z2.x + cf.y * z2.y;
            acc[q2 * 2 + 1] += cf.x * z2.z + cf.y * z2.w;
        }
    }
    float* dst = out + ((size_t)bi * Xx + xx) * Tt + tc + th * 16;
#pragma unroll
    for (int q4 = 0; q4 < 4; q4++) {
        ((float4*)dst)[q4] = make_float4(acc[q4 * 4 + 0], acc[q4 * 4 + 1],
                                         acc[q4 * 4 + 2], acc[q4 * 4 + 3]);
    }
}

// ---------------- launch ----------------
extern "C" void kernel_launch(void* const* d_in, const int* in_sizes, int n_in,
                              void* d_out, int out_size) {
    const float* z0 = (const float*)d_in[0];
    const float* xi = (const float*)d_in[1];
    // d_in[2] = A : provably unused (constant-in-t term cancels in dX)
    const float* Gw = (const float*)d_in[3];
    const float* Wr = (const float*)d_in[4];
    const float* Wi = (const float*)d_in[5];

    k0_tables<<<64, 256>>>();
    k1_gu<<<Bb * Xx, 256>>>(z0, Gw);
    k2_dhu<<<Bb * Xx, 256>>>(xi);
    k3b_z0ft<<<Bb * Hh, 128>>>(z0);
    k3_dft<<<Bb * Hh * 4, 256>>>();

    kp_a<<<Xx * Bb, 256>>>();
    kp_b<<<Xx, 256>>>(Wr, Wi);

    cudaFuncSetAttribute(kg_mma, cudaFuncAttributeMaxDynamicSharedMemorySize,
                         KG_SMEM_BYTES);

    for (int p = 0; p < 8; p++) {
        int t0 = p * 32;
        int cnt = (p == 7) ? 31 : 32;
        kg_mma<<<Xx, 512, KG_SMEM_BYTES>>>(t0);
        ks_scan<<<Xx, 256>>>(t0, cnt);
    }

    k5_idft<<<Bb * Hh * 8, 256>>>((float*)d_out);
}